// round 3
// baseline (speedup 1.0000x reference)
#include <cuda_runtime.h>
#include <math.h>

#define B_  256
#define L_  256
#define D_  128
#define H_  256
#define G4_ 1024
#define BL_ (B_*L_)

// ---------------- device scratch (static; no allocations anywhere) -------------
__device__ float g_gamma_h[BL_*H_];            // 64 MB : exp(-relu(d@tdhW^T+b)) per (b,t)
__device__ float g_alpha  [BL_*D_];            // 32 MB : [gamma_x,m]@wcW^T+b per (b,t)
__device__ float g_gpre   [(size_t)BL_*G4_];   // 256 MB: m@W_ihB^T + b_ih + b_hh
__device__ float g_Whh_t  [H_*G4_];            // W_hh transposed to [k][n]
__device__ float g_WihA_t [D_*G4_];            // W_ih[:, :128]^T  -> [k][n]
__device__ float g_WihB_t [D_*G4_];            // W_ih[:, 128:]^T  -> [k][n]
__device__ float g_hist_t [H_*D_];             // hist_W^T [k][d]
__device__ float g_feat_t [D_*D_];             // (feat_W * (1-eye))^T [k][d]
__device__ float g_tdh_t  [D_*H_];             // td_h_W^T [d][j]
__device__ float g_wc_t   [(2*D_)*D_];         // wc_W^T [k][dn]
__device__ float g_bias   [G4_];               // b_ih + b_hh
__device__ float g_num    [L_];
__device__ float g_den    [L_];

// ---------------- K0: weight transposes + zero g_num ---------------------------
__global__ void k_prep(const float* __restrict__ hist_W, const float* __restrict__ feat_W,
                       const float* __restrict__ W_ih,   const float* __restrict__ W_hh,
                       const float* __restrict__ td_h_W, const float* __restrict__ wc_W,
                       const float* __restrict__ b_ih,   const float* __restrict__ b_hh)
{
    int idx = blockIdx.x * blockDim.x + threadIdx.x;
    int stride = gridDim.x * blockDim.x;
    for (int i = idx; i < H_*G4_; i += stride) {          // W_hh (1024,256) -> [k][n]
        int k = i / G4_, n = i % G4_;
        g_Whh_t[i] = W_hh[n*H_ + k];
    }
    for (int i = idx; i < D_*G4_; i += stride) {          // W_ih (1024,256) split halves
        int k = i / G4_, n = i % G4_;
        g_WihA_t[i] = W_ih[n*(2*D_) + k];
        g_WihB_t[i] = W_ih[n*(2*D_) + D_ + k];
    }
    for (int i = idx; i < H_*D_; i += stride) {           // hist_W (128,256) -> [k][d]
        int k = i / D_, d = i % D_;
        g_hist_t[i] = hist_W[d*H_ + k];
    }
    for (int i = idx; i < D_*D_; i += stride) {           // feat_W (128,128), zero diag
        int k = i / D_, d = i % D_;
        g_feat_t[i] = (k == d) ? 0.f : feat_W[d*D_ + k];
    }
    for (int i = idx; i < D_*H_; i += stride) {           // td_h_W (256,128) -> [d][j]
        int d = i / H_, j = i % H_;
        g_tdh_t[i] = td_h_W[j*D_ + d];
    }
    for (int i = idx; i < (2*D_)*D_; i += stride) {       // wc_W (128,256) -> [k][dn]
        int k = i / D_, dn = i % D_;
        g_wc_t[i] = wc_W[dn*(2*D_) + k];
    }
    for (int i = idx; i < G4_; i += stride) g_bias[i] = b_ih[i] + b_hh[i];
    for (int i = idx; i < L_;  i += stride) g_num[i] = 0.f;
}

// ---------------- K0b: per-timestep loss denominator ----------------------------
__global__ void k_den(const float* __restrict__ evalm)
{
    int t = blockIdx.x;
    int tid = threadIdx.x;                   // 128 threads, tid = d
    float s = 0.f;
    for (int b = 0; b < B_; b++)
        s += evalm[((size_t)b*L_ + t)*D_ + tid];
    #pragma unroll
    for (int off = 16; off > 0; off >>= 1)
        s += __shfl_down_sync(0xffffffffu, s, off);
    __shared__ float red[4];
    if ((tid & 31) == 0) red[tid >> 5] = s;
    __syncthreads();
    if (tid == 0) g_den[t] = red[0] + red[1] + red[2] + red[3];
}

// ---------------- K1: gamma_h precompute (BL rows, 16 rows/CTA) -----------------
__global__ void __launch_bounds__(256) k_gamma_h(const float* __restrict__ deltas,
                                                 const float* __restrict__ td_h_b)
{
    __shared__ float sd[16][D_];
    int bl0 = blockIdx.x * 16;
    int tid = threadIdx.x;
    #pragma unroll
    for (int i = 0; i < 8; i++) {
        int idx = tid + i*256;
        int r = idx >> 7, d = idx & 127;
        sd[r][d] = deltas[(size_t)(bl0 + r)*D_ + d];
    }
    __syncthreads();
    int j = tid;
    float acc[16];
    float b = td_h_b[j];
    #pragma unroll
    for (int r = 0; r < 16; r++) acc[r] = b;
    #pragma unroll 4
    for (int d = 0; d < D_; d++) {
        float w = g_tdh_t[d*H_ + j];
        #pragma unroll
        for (int r = 0; r < 16; r++) acc[r] += sd[r][d] * w;
    }
    #pragma unroll
    for (int r = 0; r < 16; r++)
        g_gamma_h[(size_t)(bl0 + r)*H_ + j] = expf(-fmaxf(acc[r], 0.f));
}

// ---------------- K2: alpha precompute ------------------------------------------
__global__ void __launch_bounds__(128) k_alpha(const float* __restrict__ deltas,
                                               const float* __restrict__ masks,
                                               const float* __restrict__ td_x_w,
                                               const float* __restrict__ td_x_b,
                                               const float* __restrict__ wc_b)
{
    __shared__ float sin_[16][2*D_];
    int bl0 = blockIdx.x * 16;
    int tid = threadIdx.x;
    #pragma unroll
    for (int i = 0; i < 32; i++) {
        int idx = tid + i*128;
        int r = idx >> 8, k = idx & 255;
        float v;
        if (k < D_) {
            float dd = deltas[(size_t)(bl0 + r)*D_ + k];
            v = expf(-fmaxf(dd*td_x_w[k] + td_x_b[k], 0.f));   // gamma_x
        } else {
            v = masks[(size_t)(bl0 + r)*D_ + (k - D_)];
        }
        sin_[r][k] = v;
    }
    __syncthreads();
    int dn = tid;
    float acc[16];
    float b = wc_b[dn];
    #pragma unroll
    for (int r = 0; r < 16; r++) acc[r] = b;
    #pragma unroll 4
    for (int k = 0; k < 2*D_; k++) {
        float w = g_wc_t[k*D_ + dn];
        #pragma unroll
        for (int r = 0; r < 16; r++) acc[r] += sin_[r][k] * w;
    }
    #pragma unroll
    for (int r = 0; r < 16; r++)
        g_alpha[(size_t)(bl0 + r)*D_ + dn] = acc[r];
}

// ---------------- K3: gates m-half precompute (8 rows/CTA) ----------------------
__global__ void __launch_bounds__(256) k_gpre(const float* __restrict__ masks)
{
    __shared__ float sm[8][D_];
    int bl0 = blockIdx.x * 8;
    int tid = threadIdx.x;
    #pragma unroll
    for (int i = 0; i < 4; i++) {
        int idx = tid + i*256;
        int r = idx >> 7, d = idx & 127;
        sm[r][d] = masks[(size_t)(bl0 + r)*D_ + d];
    }
    __syncthreads();
    int n = tid * 4;
    float4 bias = *(const float4*)&g_bias[n];
    float4 acc[8];
    #pragma unroll
    for (int r = 0; r < 8; r++) acc[r] = bias;
    #pragma unroll 2
    for (int k = 0; k < D_; k++) {
        float4 w = *(const float4*)&g_WihB_t[k*G4_ + n];
        #pragma unroll
        for (int r = 0; r < 8; r++) {
            float mv = sm[r][k];
            acc[r].x += mv*w.x; acc[r].y += mv*w.y;
            acc[r].z += mv*w.z; acc[r].w += mv*w.w;
        }
    }
    #pragma unroll
    for (int r = 0; r < 8; r++)
        *(float4*)&g_gpre[((size_t)(bl0 + r))*G4_ + n] = acc[r];
}

// ---------------- K4: main sequential recurrence (2 batch rows / CTA) -----------
__global__ void __launch_bounds__(256) k_main(const float* __restrict__ values,
                                              const float* __restrict__ masks,
                                              const float* __restrict__ evalm,
                                              const float* __restrict__ hist_b,
                                              const float* __restrict__ feat_b,
                                              float* __restrict__ out)
{
    __shared__ float sh_h[2][H_], sh_c[2][H_], sh_hd[2][H_];
    __shared__ float sh_x[2][D_], sh_m[2][D_], sh_xh[2][D_], sh_xc[2][D_], sh_cc[2][D_];
    __shared__ float sh_g[2][G4_];
    __shared__ float sh_hb[D_], sh_fb[D_];
    __shared__ float sh_num;

    int tid = threadIdx.x;
    int b0  = blockIdx.x * 2;
    int r_  = tid >> 7;
    int d_  = tid & 127;

    sh_h[0][tid] = 0.f; sh_h[1][tid] = 0.f;
    sh_c[0][tid] = 0.f; sh_c[1][tid] = 0.f;
    if (tid < D_) { sh_hb[tid] = hist_b[tid]; sh_fb[tid] = feat_b[tid]; }
    __syncthreads();

    for (int t = 0; t < L_; t++) {
        // ---- phase 0: load x,m ; decay h ----
        if (tid == 0) sh_num = 0.f;
        int base_rd = ((b0 + r_)*L_ + t)*D_ + d_;
        sh_x[r_][d_] = values[base_rd];
        sh_m[r_][d_] = masks[base_rd];
        {
            int gb0 = ((b0    )*L_ + t)*H_;
            int gb1 = ((b0 + 1)*L_ + t)*H_;
            sh_hd[0][tid] = sh_h[0][tid] * g_gamma_h[gb0 + tid];
            sh_hd[1][tid] = sh_h[1][tid] * g_gamma_h[gb1 + tid];
        }
        __syncthreads();

        // ---- phase 1: x_h = hd @ hist_W^T + b ; x_c ----
        {
            float acc = sh_hb[d_];
            #pragma unroll 8
            for (int k = 0; k < H_; k++)
                acc += sh_hd[r_][k] * g_hist_t[k*D_ + d_];
            sh_xh[r_][d_] = acc;
            float mv = sh_m[r_][d_], xv = sh_x[r_][d_];
            sh_xc[r_][d_] = mv*xv + (1.f - mv)*acc;
        }
        __syncthreads();

        // ---- phase 2: z_h, c_h, c_c, imputation out, loss partial ----
        {
            float acc = sh_fb[d_];
            #pragma unroll 8
            for (int k = 0; k < D_; k++)
                acc += sh_xc[r_][k] * g_feat_t[k*D_ + d_];
            float al = g_alpha[base_rd];
            float xh = sh_xh[r_][d_];
            float ch = al*acc + (1.f - al)*xh;
            float mv = sh_m[r_][d_], xv = sh_x[r_][d_];
            float cc = mv*xv + (1.f - mv)*ch;
            sh_cc[r_][d_] = cc;
            out[base_rd]  = cc;
            float me = evalm[base_rd];
            float p  = fabsf(cc - xv) * me;
            #pragma unroll
            for (int off = 16; off > 0; off >>= 1)
                p += __shfl_down_sync(0xffffffffu, p, off);
            if ((tid & 31) == 0) atomicAdd(&sh_num, p);
        }
        __syncthreads();

        // ---- phase 3: gates = gpre + hd@W_hh^T + cc@W_ihA^T ----
        {
            int n = tid * 4;
            size_t pb0 = ((size_t)(b0    )*L_ + t)*G4_ + n;
            size_t pb1 = ((size_t)(b0 + 1)*L_ + t)*G4_ + n;
            float4 a0 = *(const float4*)&g_gpre[pb0];
            float4 a1 = *(const float4*)&g_gpre[pb1];
            #pragma unroll 4
            for (int k = 0; k < H_; k++) {
                float4 w = *(const float4*)&g_Whh_t[k*G4_ + n];
                float h0 = sh_hd[0][k], h1 = sh_hd[1][k];
                a0.x += h0*w.x; a0.y += h0*w.y; a0.z += h0*w.z; a0.w += h0*w.w;
                a1.x += h1*w.x; a1.y += h1*w.y; a1.z += h1*w.z; a1.w += h1*w.w;
            }
            #pragma unroll 4
            for (int k = 0; k < D_; k++) {
                float4 w = *(const float4*)&g_WihA_t[k*G4_ + n];
                float c0 = sh_cc[0][k], c1 = sh_cc[1][k];
                a0.x += c0*w.x; a0.y += c0*w.y; a0.z += c0*w.z; a0.w += c0*w.w;
                a1.x += c1*w.x; a1.y += c1*w.y; a1.z += c1*w.z; a1.w += c1*w.w;
            }
            *(float4*)&sh_g[0][n] = a0;
            *(float4*)&sh_g[1][n] = a1;
            if (tid == 0) atomicAdd(&g_num[t], sh_num);   // sh_num final after phase-2 sync
        }
        __syncthreads();

        // ---- phase 4: LSTM elementwise ----
        {
            #pragma unroll
            for (int r = 0; r < 2; r++) {
                float ig = sh_g[r][tid];
                float fg = sh_g[r][H_   + tid];
                float gg = sh_g[r][2*H_ + tid];
                float og = sh_g[r][3*H_ + tid];
                ig = 1.f / (1.f + expf(-ig));
                fg = 1.f / (1.f + expf(-fg));
                og = 1.f / (1.f + expf(-og));
                gg = tanhf(gg);
                float c = fg*sh_c[r][tid] + ig*gg;
                sh_c[r][tid] = c;
                sh_h[r][tid] = og * tanhf(c);
            }
        }
        __syncthreads();
    }
}

// ---------------- K5: finalize loss ---------------------------------------------
__global__ void k_fin(float* __restrict__ out, int out_size)
{
    int t = threadIdx.x;            // 256
    float v = g_num[t] / (g_den[t] + 1e-5f);
    #pragma unroll
    for (int off = 16; off > 0; off >>= 1)
        v += __shfl_down_sync(0xffffffffu, v, off);
    __shared__ float red[8];
    if ((t & 31) == 0) red[t >> 5] = v;
    __syncthreads();
    if (t == 0) {
        float s = 0.f;
        #pragma unroll
        for (int i = 0; i < 8; i++) s += red[i];
        if (out_size > B_*L_*D_) out[B_*L_*D_] = s;   // IMPUTE_WEIGHT = 1.0
    }
}

// ---------------- launch ---------------------------------------------------------
extern "C" void kernel_launch(void* const* d_in, const int* in_sizes, int n_in,
                              void* d_out, int out_size)
{
    const float* values = (const float*)d_in[0];
    const float* masks  = (const float*)d_in[1];
    const float* deltas = (const float*)d_in[2];
    const float* evalm  = (const float*)d_in[3];
    const float* td_h_W = (const float*)d_in[4];
    const float* td_h_b = (const float*)d_in[5];
    const float* td_x_w = (const float*)d_in[6];
    const float* td_x_b = (const float*)d_in[7];
    const float* hist_W = (const float*)d_in[8];
    const float* hist_b = (const float*)d_in[9];
    const float* feat_W = (const float*)d_in[10];
    const float* feat_b = (const float*)d_in[11];
    const float* wc_W   = (const float*)d_in[12];
    const float* wc_b   = (const float*)d_in[13];
    const float* W_ih   = (const float*)d_in[14];
    const float* W_hh   = (const float*)d_in[15];
    const float* b_ih   = (const float*)d_in[16];
    const float* b_hh   = (const float*)d_in[17];
    float* out = (float*)d_out;

    k_prep   <<<256, 256>>>(hist_W, feat_W, W_ih, W_hh, td_h_W, wc_W, b_ih, b_hh);
    k_den    <<<L_, 128>>>(evalm);
    k_gamma_h<<<BL_/16, 256>>>(deltas, td_h_b);
    k_alpha  <<<BL_/16, 128>>>(deltas, masks, td_x_w, td_x_b, wc_b);
    k_gpre   <<<BL_/8, 256>>>(masks);
    k_main   <<<B_/2, 256>>>(values, masks, evalm, hist_b, feat_b, out);
    k_fin    <<<1, 256>>>(out, out_size);
}

// round 4
// speedup vs baseline: 1.7951x; 1.7951x over previous
#include <cuda_runtime.h>
#include <math.h>
#include <stdint.h>

#define B_  256
#define L_  256
#define D_  128
#define H_  256
#define G4_ 1024
#define BL_ (B_*L_)

// ---------------- device scratch (static; no allocations anywhere) -------------
__device__ float g_gamma_h[BL_*H_];            // 64 MB
__device__ float g_alpha  [BL_*D_];            // 32 MB
__device__ float g_gpre   [(size_t)BL_*G4_];   // 256 MB (PERMUTED gate columns)
__device__ float g_Whh_t  [H_*G4_];            // [k][n'] permuted
__device__ float g_WihA_t [D_*G4_];            // [k][n'] permuted
__device__ float g_WihB_t [D_*G4_];            // [k][n'] permuted
__device__ float g_hist_t [H_*D_];             // [k][d]
__device__ float g_feat_t [D_*D_];             // [k][d], zero diag
__device__ float g_tdh_t  [D_*H_];             // [d][j]
__device__ float g_wc_t   [(2*D_)*D_];         // [k][dn]
__device__ float g_bias   [G4_];               // permuted b_ih+b_hh
__device__ float g_num    [L_];
__device__ float g_den    [L_];

// gate-column permutation: n' = q*256 + g*64 + jj  <->  n = g*256 + q*64 + jj
__device__ __forceinline__ int permN(int np) {
    return ((np >> 6) & 3) * 256 + (np >> 8) * 64 + (np & 63);
}

// ---------------- K0: weight transposes (permuted) + zero g_num -----------------
__global__ void k_prep(const float* __restrict__ hist_W, const float* __restrict__ feat_W,
                       const float* __restrict__ W_ih,   const float* __restrict__ W_hh,
                       const float* __restrict__ td_h_W, const float* __restrict__ wc_W,
                       const float* __restrict__ b_ih,   const float* __restrict__ b_hh)
{
    int idx = blockIdx.x * blockDim.x + threadIdx.x;
    int stride = gridDim.x * blockDim.x;
    for (int i = idx; i < H_*G4_; i += stride) {
        int k = i >> 10, np = i & 1023;
        g_Whh_t[i] = W_hh[permN(np)*H_ + k];
    }
    for (int i = idx; i < D_*G4_; i += stride) {
        int k = i >> 10, np = i & 1023;
        int n = permN(np);
        g_WihA_t[i] = W_ih[n*(2*D_) + k];
        g_WihB_t[i] = W_ih[n*(2*D_) + D_ + k];
    }
    for (int i = idx; i < H_*D_; i += stride) {
        int k = i / D_, d = i % D_;
        g_hist_t[i] = hist_W[d*H_ + k];
    }
    for (int i = idx; i < D_*D_; i += stride) {
        int k = i / D_, d = i % D_;
        g_feat_t[i] = (k == d) ? 0.f : feat_W[d*D_ + k];
    }
    for (int i = idx; i < D_*H_; i += stride) {
        int d = i / H_, j = i % H_;
        g_tdh_t[i] = td_h_W[j*D_ + d];
    }
    for (int i = idx; i < (2*D_)*D_; i += stride) {
        int k = i / D_, dn = i % D_;
        g_wc_t[i] = wc_W[dn*(2*D_) + k];
    }
    for (int i = idx; i < G4_; i += stride) {
        int n = permN(i);
        g_bias[i] = b_ih[n] + b_hh[n];
    }
    for (int i = idx; i < L_;  i += stride) g_num[i] = 0.f;
}

// ---------------- K0b: per-timestep loss denominator ----------------------------
__global__ void k_den(const float* __restrict__ evalm)
{
    int t = blockIdx.x;
    int tid = threadIdx.x;
    float s = 0.f;
    for (int b = 0; b < B_; b++)
        s += evalm[((size_t)b*L_ + t)*D_ + tid];
    #pragma unroll
    for (int off = 16; off > 0; off >>= 1)
        s += __shfl_down_sync(0xffffffffu, s, off);
    __shared__ float red[4];
    if ((tid & 31) == 0) red[tid >> 5] = s;
    __syncthreads();
    if (tid == 0) g_den[t] = red[0] + red[1] + red[2] + red[3];
}

// ---------------- K1: gamma_h precompute ----------------------------------------
__global__ void __launch_bounds__(256) k_gamma_h(const float* __restrict__ deltas,
                                                 const float* __restrict__ td_h_b)
{
    __shared__ float sd[16][D_];
    int bl0 = blockIdx.x * 16;
    int tid = threadIdx.x;
    #pragma unroll
    for (int i = 0; i < 8; i++) {
        int idx = tid + i*256;
        int r = idx >> 7, d = idx & 127;
        sd[r][d] = deltas[(size_t)(bl0 + r)*D_ + d];
    }
    __syncthreads();
    int j = tid;
    float acc[16];
    float b = td_h_b[j];
    #pragma unroll
    for (int r = 0; r < 16; r++) acc[r] = b;
    #pragma unroll 4
    for (int d = 0; d < D_; d++) {
        float w = g_tdh_t[d*H_ + j];
        #pragma unroll
        for (int r = 0; r < 16; r++) acc[r] += sd[r][d] * w;
    }
    #pragma unroll
    for (int r = 0; r < 16; r++)
        g_gamma_h[(size_t)(bl0 + r)*H_ + j] = expf(-fmaxf(acc[r], 0.f));
}

// ---------------- K2: alpha precompute ------------------------------------------
__global__ void __launch_bounds__(128) k_alpha(const float* __restrict__ deltas,
                                               const float* __restrict__ masks,
                                               const float* __restrict__ td_x_w,
                                               const float* __restrict__ td_x_b,
                                               const float* __restrict__ wc_b)
{
    __shared__ float sin_[16][2*D_];
    int bl0 = blockIdx.x * 16;
    int tid = threadIdx.x;
    #pragma unroll
    for (int i = 0; i < 32; i++) {
        int idx = tid + i*128;
        int r = idx >> 8, k = idx & 255;
        float v;
        if (k < D_) {
            float dd = deltas[(size_t)(bl0 + r)*D_ + k];
            v = expf(-fmaxf(dd*td_x_w[k] + td_x_b[k], 0.f));
        } else {
            v = masks[(size_t)(bl0 + r)*D_ + (k - D_)];
        }
        sin_[r][k] = v;
    }
    __syncthreads();
    int dn = tid;
    float acc[16];
    float b = wc_b[dn];
    #pragma unroll
    for (int r = 0; r < 16; r++) acc[r] = b;
    #pragma unroll 4
    for (int k = 0; k < 2*D_; k++) {
        float w = g_wc_t[k*D_ + dn];
        #pragma unroll
        for (int r = 0; r < 16; r++) acc[r] += sin_[r][k] * w;
    }
    #pragma unroll
    for (int r = 0; r < 16; r++)
        g_alpha[(size_t)(bl0 + r)*D_ + dn] = acc[r];
}

// ---------------- K3: gates m-half precompute (permuted columns) -----------------
__global__ void __launch_bounds__(256) k_gpre(const float* __restrict__ masks)
{
    __shared__ float sm[8][D_];
    int bl0 = blockIdx.x * 8;
    int tid = threadIdx.x;
    #pragma unroll
    for (int i = 0; i < 4; i++) {
        int idx = tid + i*256;
        int r = idx >> 7, d = idx & 127;
        sm[r][d] = masks[(size_t)(bl0 + r)*D_ + d];
    }
    __syncthreads();
    int n = tid * 4;
    float4 bias = *(const float4*)&g_bias[n];
    float4 acc[8];
    #pragma unroll
    for (int r = 0; r < 8; r++) acc[r] = bias;
    #pragma unroll 2
    for (int k = 0; k < D_; k++) {
        float4 w = *(const float4*)&g_WihB_t[k*G4_ + n];
        #pragma unroll
        for (int r = 0; r < 8; r++) {
            float mv = sm[r][k];
            acc[r].x += mv*w.x; acc[r].y += mv*w.y;
            acc[r].z += mv*w.z; acc[r].w += mv*w.w;
        }
    }
    #pragma unroll
    for (int r = 0; r < 8; r++)
        *(float4*)&g_gpre[((size_t)(bl0 + r))*G4_ + n] = acc[r];
}

// ---------------- DSMEM helpers --------------------------------------------------
__device__ __forceinline__ uint32_t smem_u32_(const void* p) {
    uint32_t a;
    asm("{ .reg .u64 t; cvta.to.shared.u64 t, %1; cvt.u32.u64 %0, t; }"
        : "=r"(a) : "l"(p));
    return a;
}
__device__ __forceinline__ void st_dsmem(uint32_t addr, float v) {
    asm volatile("st.shared::cluster.f32 [%0], %1;" :: "r"(addr), "f"(v) : "memory");
}
#define CLUSTER_SYNC_() do { \
    asm volatile("barrier.cluster.arrive.aligned;" ::: "memory"); \
    asm volatile("barrier.cluster.wait.aligned;"  ::: "memory"); } while (0)

// SMEM layout (floats)
#define SOFF_WIHA 0
#define SOFF_HIST (SOFF_WIHA + 128*256)
#define SOFF_FEAT (SOFF_HIST + 256*32)
#define SOFF_HD   (SOFF_FEAT + 128*32)
#define SOFF_XC   (SOFF_HD   + 2*256*8)
#define SOFF_CC   (SOFF_XC   + 128*8)
#define SOFF_GT   (SOFF_CC   + 128*8)
#define SOFF_NUM  (SOFF_GT   + 8*256)
#define SMEM_FLOATS (SOFF_NUM + 16)
#define SMEM_BYTES (SMEM_FLOATS * 4)

// ---------------- K4: cluster-4 sequential recurrence ----------------------------
// 32 clusters x 4 CTAs; cluster owns 8 batch rows; rank q owns d[32q,32q+32),
// j[64q,64q+64), permuted gate columns [256q, 256q+256).
__global__ void __launch_bounds__(256) __cluster_dims__(4, 1, 1)
k_main4(const float* __restrict__ values, const float* __restrict__ masks,
        const float* __restrict__ evalm,
        const float* __restrict__ hist_b, const float* __restrict__ feat_b,
        float* __restrict__ out)
{
    extern __shared__ float smf[];
    float* s_wihA = smf + SOFF_WIHA;   // [128][256]
    float* s_hist = smf + SOFF_HIST;   // [256][32]
    float* s_feat = smf + SOFF_FEAT;   // [128][32]
    float* s_hd   = smf + SOFF_HD;     // [2][256][8]
    float* s_xc   = smf + SOFF_XC;     // [128][8]
    float* s_cc   = smf + SOFF_CC;     // [128][8]
    float* s_gt   = smf + SOFF_GT;     // [8][256]
    float* s_num  = smf + SOFF_NUM;

    const int tid = threadIdx.x;
    uint32_t q;
    asm("mov.u32 %0, %%cluster_ctarank;" : "=r"(q));
    const int b0 = (blockIdx.x >> 2) * 8;

    // preload stationary weight slices
    #pragma unroll 4
    for (int i = tid; i < 128*256; i += 256) {
        int k = i >> 8, nn = i & 255;
        s_wihA[i] = g_WihA_t[k*G4_ + (int)q*256 + nn];
    }
    #pragma unroll 4
    for (int i = tid; i < 256*32; i += 256) {
        int k = i >> 5, dd = i & 31;
        s_hist[i] = g_hist_t[k*D_ + (int)q*32 + dd];
    }
    #pragma unroll 4
    for (int i = tid; i < 128*32; i += 256) {
        int k = i >> 5, dd = i & 31;
        s_feat[i] = g_feat_t[k*D_ + (int)q*32 + dd];
    }
    if (tid == 0) s_num[0] = 0.f;
    __syncthreads();

    // remote SMEM bases for the 4 ranks
    uint32_t sbase = smem_u32_(smf);
    uint32_t rb0, rb1, rb2, rb3;
    asm("mapa.shared::cluster.u32 %0, %1, %2;" : "=r"(rb0) : "r"(sbase), "r"(0u));
    asm("mapa.shared::cluster.u32 %0, %1, %2;" : "=r"(rb1) : "r"(sbase), "r"(1u));
    asm("mapa.shared::cluster.u32 %0, %1, %2;" : "=r"(rb2) : "r"(sbase), "r"(2u));
    asm("mapa.shared::cluster.u32 %0, %1, %2;" : "=r"(rb3) : "r"(sbase), "r"(3u));

    // thread mappings
    const int r1 = tid >> 5;            // row 0..7 (one row per warp)
    const int dd = tid & 31;            // within-slice d
    const int dg = (int)q*32 + dd;      // global d
    const int jjA = dd*2, jgA = (int)q*64 + jjA;   // two owned h-indices
    const float hb = hist_b[dg], fb = feat_b[dg];

    float hA = 0.f, hB = 0.f, cA = 0.f, cB = 0.f;

    for (int t = 0; t < L_; t++) {
        const int par = t & 1;
        // ---- P0: decay h, push hd slices to all ranks ----
        {
            const float2 gg = *(const float2*)&g_gamma_h[((size_t)(b0+r1)*L_ + t)*H_ + jgA];
            float hdA = hA * gg.x;
            float hdB = hB * gg.y;
            uint32_t oA = (uint32_t)(SOFF_HD + ((par*256 + jgA)*8 + r1)) * 4u;
            uint32_t oB = oA + 32u;  // jgA+1 -> +8 floats
            st_dsmem(rb0 + oA, hdA); st_dsmem(rb0 + oB, hdB);
            st_dsmem(rb1 + oA, hdA); st_dsmem(rb1 + oB, hdB);
            st_dsmem(rb2 + oA, hdA); st_dsmem(rb2 + oB, hdB);
            st_dsmem(rb3 + oA, hdA); st_dsmem(rb3 + oB, hdB);
        }
        CLUSTER_SYNC_();

        // ---- P1: x_h = hd @ hist^T (own d's); xc; push xc ----
        const size_t ib = ((size_t)(b0+r1)*L_ + t)*D_ + dg;
        const float xv = values[ib];
        const float mv = masks[ib];
        float xh;
        {
            const float* hdp = &s_hd[par*256*8 + r1];
            float a0 = hb, a1 = 0.f;
            #pragma unroll 8
            for (int k = 0; k < 256; k += 2) {
                a0 += hdp[k*8]     * s_hist[k*32 + dd];
                a1 += hdp[(k+1)*8] * s_hist[(k+1)*32 + dd];
            }
            xh = a0 + a1;
        }
        const float xc = mv*xv + (1.f - mv)*xh;
        {
            uint32_t o = (uint32_t)(SOFF_XC + (dg*8 + r1)) * 4u;
            st_dsmem(rb0 + o, xc); st_dsmem(rb1 + o, xc);
            st_dsmem(rb2 + o, xc); st_dsmem(rb3 + o, xc);
        }
        CLUSTER_SYNC_();

        // ---- P2: z_h, c_h, c_c, imputation, loss; push cc ----
        float cc;
        {
            float a0 = fb, a1 = 0.f;
            #pragma unroll 8
            for (int k = 0; k < 128; k += 2) {
                a0 += s_xc[k*8 + r1]     * s_feat[k*32 + dd];
                a1 += s_xc[(k+1)*8 + r1] * s_feat[(k+1)*32 + dd];
            }
            float zh = a0 + a1;
            float al = g_alpha[ib];
            float ch = al*zh + (1.f - al)*xh;
            cc = mv*xv + (1.f - mv)*ch;
            out[ib] = cc;
            float me = evalm[ib];
            float p = fabsf(cc - xv) * me;
            #pragma unroll
            for (int off = 16; off > 0; off >>= 1)
                p += __shfl_down_sync(0xffffffffu, p, off);
            if (dd == 0) atomicAdd(s_num, p);
            uint32_t o = (uint32_t)(SOFF_CC + (dg*8 + r1)) * 4u;
            st_dsmem(rb0 + o, cc); st_dsmem(rb1 + o, cc);
            st_dsmem(rb2 + o, cc); st_dsmem(rb3 + o, cc);
        }
        CLUSTER_SYNC_();

        // ---- P3: gates = gpre + hd@Whh-slice + cc@WihA-slice (own 256 n') ----
        if (tid == 0) {
            atomicAdd(&g_num[t], s_num[0]);
            s_num[0] = 0.f;
        }
        float acc[8];
        {
            const float* gp = &g_gpre[((size_t)b0*L_ + t)*G4_ + (int)q*256 + tid];
            #pragma unroll
            for (int r = 0; r < 8; r++) acc[r] = gp[(size_t)r*L_*G4_];
        }
        {
            const float*  wp  = &g_Whh_t[(int)q*256 + tid];
            const float4* hdp = (const float4*)&s_hd[par*256*8];
            #pragma unroll 8
            for (int k = 0; k < 256; k++) {
                float  w = wp[k*G4_];
                float4 u = hdp[k*2];
                float4 v = hdp[k*2 + 1];
                acc[0] += u.x*w; acc[1] += u.y*w; acc[2] += u.z*w; acc[3] += u.w*w;
                acc[4] += v.x*w; acc[5] += v.y*w; acc[6] += v.z*w; acc[7] += v.w*w;
            }
        }
        {
            const float4* ccp = (const float4*)s_cc;
            #pragma unroll 8
            for (int k = 0; k < 128; k++) {
                float  w = s_wihA[k*256 + tid];
                float4 u = ccp[k*2];
                float4 v = ccp[k*2 + 1];
                acc[0] += u.x*w; acc[1] += u.y*w; acc[2] += u.z*w; acc[3] += u.w*w;
                acc[4] += v.x*w; acc[5] += v.y*w; acc[6] += v.z*w; acc[7] += v.w*w;
            }
        }
        #pragma unroll
        for (int r = 0; r < 8; r++) s_gt[r*256 + tid] = acc[r];
        __syncthreads();

        // ---- P4: LSTM elementwise for own (row r1, j = jgA, jgA+1) ----
        {
            const float* gr = &s_gt[r1*256];
            float i0 = gr[jjA],      f0 = gr[64 + jjA];
            float g0 = gr[128 + jjA], o0 = gr[192 + jjA];
            float i1 = gr[jjA + 1],   f1 = gr[64 + jjA + 1];
            float g1 = gr[128 + jjA + 1], o1 = gr[192 + jjA + 1];
            i0 = 1.f/(1.f + expf(-i0)); f0 = 1.f/(1.f + expf(-f0));
            o0 = 1.f/(1.f + expf(-o0)); g0 = tanhf(g0);
            i1 = 1.f/(1.f + expf(-i1)); f1 = 1.f/(1.f + expf(-f1));
            o1 = 1.f/(1.f + expf(-o1)); g1 = tanhf(g1);
            cA = f0*cA + i0*g0;  hA = o0*tanhf(cA);
            cB = f1*cB + i1*g1;  hB = o1*tanhf(cB);
        }
        // no extra barrier needed: next P0 writes only s_hd[par^1] (double-buffered),
        // and s_gt is rewritten only after 3 cluster syncs.
    }
}

// ---------------- K5: finalize loss ---------------------------------------------
__global__ void k_fin(float* __restrict__ out, int out_size)
{
    int t = threadIdx.x;
    float v = g_num[t] / (g_den[t] + 1e-5f);
    #pragma unroll
    for (int off = 16; off > 0; off >>= 1)
        v += __shfl_down_sync(0xffffffffu, v, off);
    __shared__ float red[8];
    if ((t & 31) == 0) red[t >> 5] = v;
    __syncthreads();
    if (t == 0) {
        float s = 0.f;
        #pragma unroll
        for (int i = 0; i < 8; i++) s += red[i];
        if (out_size > B_*L_*D_) out[B_*L_*D_] = s;
    }
}

// ---------------- launch ----------------------------------------------------------
extern "C" void kernel_launch(void* const* d_in, const int* in_sizes, int n_in,
                              void* d_out, int out_size)
{
    const float* values = (const float*)d_in[0];
    const float* masks  = (const float*)d_in[1];
    const float* deltas = (const float*)d_in[2];
    const float* evalm  = (const float*)d_in[3];
    const float* td_h_W = (const float*)d_in[4];
    const float* td_h_b = (const float*)d_in[5];
    const float* td_x_w = (const float*)d_in[6];
    const float* td_x_b = (const float*)d_in[7];
    const float* hist_W = (const float*)d_in[8];
    const float* hist_b = (const float*)d_in[9];
    const float* feat_W = (const float*)d_in[10];
    const float* feat_b = (const float*)d_in[11];
    const float* wc_W   = (const float*)d_in[12];
    const float* wc_b   = (const float*)d_in[13];
    const float* W_ih   = (const float*)d_in[14];
    const float* W_hh   = (const float*)d_in[15];
    const float* b_ih   = (const float*)d_in[16];
    const float* b_hh   = (const float*)d_in[17];
    float* out = (float*)d_out;

    cudaFuncSetAttribute(k_main4, cudaFuncAttributeMaxDynamicSharedMemorySize, SMEM_BYTES);

    k_prep   <<<256, 256>>>(hist_W, feat_W, W_ih, W_hh, td_h_W, wc_W, b_ih, b_hh);
    k_den    <<<L_, 128>>>(evalm);
    k_gamma_h<<<BL_/16, 256>>>(deltas, td_h_b);
    k_alpha  <<<BL_/16, 128>>>(deltas, masks, td_x_w, td_x_b, wc_b);
    k_gpre   <<<BL_/8, 256>>>(masks);
    k_main4  <<<128, 256, SMEM_BYTES>>>(values, masks, evalm, hist_b, feat_b, out);
    k_fin    <<<1, 256>>>(out, out_size);
}

// round 5
// speedup vs baseline: 2.3696x; 1.3200x over previous
#include <cuda_runtime.h>
#include <math.h>
#include <stdint.h>

#define B_  256
#define L_  256
#define D_  128
#define H_  256
#define G4_ 1024
#define BL_ (B_*L_)

typedef unsigned long long ull;

// ---------------- f32x2 helpers ---------------------------------------------------
#define FMA2(d,a,b,c) asm("fma.rn.f32x2 %0, %1, %2, %3;" : "=l"(d) : "l"(a), "l"(b), "l"(c))
__device__ __forceinline__ ull bcast2(float v){ ull d; asm("mov.b64 %0, {%1, %1};" : "=l"(d) : "f"(v)); return d; }
__device__ __forceinline__ ull pack2(float lo, float hi){ ull d; asm("mov.b64 %0, {%1, %2};" : "=l"(d) : "f"(lo), "f"(hi)); return d; }
__device__ __forceinline__ float2 unpack2(ull d){ float lo,hi; asm("mov.b64 {%0, %1}, %2;" : "=f"(lo), "=f"(hi) : "l"(d)); return make_float2(lo,hi); }

// ---------------- device scratch (static; no allocations anywhere) ----------------
__device__ float g_gamma_h[BL_*H_];            // 64 MB
__device__ float g_alpha  [BL_*D_];            // 32 MB
__device__ float g_gpre   [(size_t)BL_*G4_];   // 256 MB (PERMUTED gate columns)
__device__ float g_Whh_t  [H_*G4_];            // [k][n'] permuted
__device__ float g_WihA_t [D_*G4_];            // [k][n'] permuted
__device__ float g_WihB_t [D_*G4_];            // [k][n'] permuted
__device__ float g_tdh_t  [D_*H_];             // [d][j]
__device__ float g_wc_t   [(2*D_)*D_];         // [k][dn]
__device__ float g_bias   [G4_];               // permuted b_ih+b_hh
__device__ float g_num    [L_];
__device__ float g_den    [L_];

// gate-column permutation: n' = q*256 + g*64 + jj  <->  n = g*256 + q*64 + jj
__device__ __forceinline__ int permN(int np) {
    return ((np >> 6) & 3) * 256 + (np >> 8) * 64 + (np & 63);
}

// ---------------- K0: weight transposes (permuted) + zero g_num -------------------
__global__ void k_prep(const float* __restrict__ W_ih,   const float* __restrict__ W_hh,
                       const float* __restrict__ td_h_W, const float* __restrict__ wc_W,
                       const float* __restrict__ b_ih,   const float* __restrict__ b_hh)
{
    int idx = blockIdx.x * blockDim.x + threadIdx.x;
    int stride = gridDim.x * blockDim.x;
    for (int i = idx; i < H_*G4_; i += stride) {
        int k = i >> 10, np = i & 1023;
        g_Whh_t[i] = W_hh[permN(np)*H_ + k];
    }
    for (int i = idx; i < D_*G4_; i += stride) {
        int k = i >> 10, np = i & 1023;
        int n = permN(np);
        g_WihA_t[i] = W_ih[n*(2*D_) + k];
        g_WihB_t[i] = W_ih[n*(2*D_) + D_ + k];
    }
    for (int i = idx; i < D_*H_; i += stride) {
        int d = i / H_, j = i % H_;
        g_tdh_t[i] = td_h_W[j*D_ + d];
    }
    for (int i = idx; i < (2*D_)*D_; i += stride) {
        int k = i / D_, dn = i % D_;
        g_wc_t[i] = wc_W[dn*(2*D_) + k];
    }
    for (int i = idx; i < G4_; i += stride) {
        int n = permN(i);
        g_bias[i] = b_ih[n] + b_hh[n];
    }
    for (int i = idx; i < L_;  i += stride) g_num[i] = 0.f;
}

// ---------------- K0b: per-timestep loss denominator ------------------------------
__global__ void k_den(const float* __restrict__ evalm)
{
    int t = blockIdx.x;
    int tid = threadIdx.x;
    float s = 0.f;
    for (int b = 0; b < B_; b++)
        s += evalm[((size_t)b*L_ + t)*D_ + tid];
    #pragma unroll
    for (int off = 16; off > 0; off >>= 1)
        s += __shfl_down_sync(0xffffffffu, s, off);
    __shared__ float red[4];
    if ((tid & 31) == 0) red[tid >> 5] = s;
    __syncthreads();
    if (tid == 0) g_den[t] = red[0] + red[1] + red[2] + red[3];
}

// ---------------- K1: gamma_h precompute -------------------------------------------
__global__ void __launch_bounds__(256) k_gamma_h(const float* __restrict__ deltas,
                                                 const float* __restrict__ td_h_b)
{
    __shared__ float sd[16][D_];
    int bl0 = blockIdx.x * 16;
    int tid = threadIdx.x;
    #pragma unroll
    for (int i = 0; i < 8; i++) {
        int idx = tid + i*256;
        int r = idx >> 7, d = idx & 127;
        sd[r][d] = deltas[(size_t)(bl0 + r)*D_ + d];
    }
    __syncthreads();
    int j = tid;
    float acc[16];
    float b = td_h_b[j];
    #pragma unroll
    for (int r = 0; r < 16; r++) acc[r] = b;
    #pragma unroll 4
    for (int d = 0; d < D_; d++) {
        float w = g_tdh_t[d*H_ + j];
        #pragma unroll
        for (int r = 0; r < 16; r++) acc[r] += sd[r][d] * w;
    }
    #pragma unroll
    for (int r = 0; r < 16; r++)
        g_gamma_h[(size_t)(bl0 + r)*H_ + j] = __expf(-fmaxf(acc[r], 0.f));
}

// ---------------- K2: alpha precompute ---------------------------------------------
__global__ void __launch_bounds__(128) k_alpha(const float* __restrict__ deltas,
                                               const float* __restrict__ masks,
                                               const float* __restrict__ td_x_w,
                                               const float* __restrict__ td_x_b,
                                               const float* __restrict__ wc_b)
{
    __shared__ float sin_[16][2*D_];
    int bl0 = blockIdx.x * 16;
    int tid = threadIdx.x;
    #pragma unroll
    for (int i = 0; i < 32; i++) {
        int idx = tid + i*128;
        int r = idx >> 8, k = idx & 255;
        float v;
        if (k < D_) {
            float dd = deltas[(size_t)(bl0 + r)*D_ + k];
            v = __expf(-fmaxf(dd*td_x_w[k] + td_x_b[k], 0.f));
        } else {
            v = masks[(size_t)(bl0 + r)*D_ + (k - D_)];
        }
        sin_[r][k] = v;
    }
    __syncthreads();
    int dn = tid;
    float acc[16];
    float b = wc_b[dn];
    #pragma unroll
    for (int r = 0; r < 16; r++) acc[r] = b;
    #pragma unroll 4
    for (int k = 0; k < 2*D_; k++) {
        float w = g_wc_t[k*D_ + dn];
        #pragma unroll
        for (int r = 0; r < 16; r++) acc[r] += sin_[r][k] * w;
    }
    #pragma unroll
    for (int r = 0; r < 16; r++)
        g_alpha[(size_t)(bl0 + r)*D_ + dn] = acc[r];
}

// ---------------- K3: gates m-half precompute (permuted cols, f32x2) ----------------
__global__ void __launch_bounds__(256) k_gpre(const float* __restrict__ masks)
{
    __shared__ float sm[D_*8];      // [d][row]
    int bl0 = blockIdx.x * 8;
    int tid = threadIdx.x;
    #pragma unroll
    for (int i = 0; i < 4; i++) {
        int idx = tid + i*256;
        int r = idx >> 7, d = idx & 127;
        sm[d*8 + r] = masks[(size_t)(bl0 + r)*D_ + d];
    }
    __syncthreads();
    int n4 = tid * 4;
    float4 bias4 = *(const float4*)&g_bias[n4];
    ull acc[4][4];                  // [rowpair][col]
    #pragma unroll
    for (int rp = 0; rp < 4; rp++) {
        acc[rp][0] = bcast2(bias4.x); acc[rp][1] = bcast2(bias4.y);
        acc[rp][2] = bcast2(bias4.z); acc[rp][3] = bcast2(bias4.w);
    }
    #pragma unroll 4
    for (int k = 0; k < D_; k++) {
        float4 w = *(const float4*)&g_WihB_t[k*G4_ + n4];
        ull pw0 = bcast2(w.x), pw1 = bcast2(w.y), pw2 = bcast2(w.z), pw3 = bcast2(w.w);
        ulonglong2 mA = *(const ulonglong2*)&sm[k*8];
        ulonglong2 mB = *(const ulonglong2*)&sm[k*8 + 4];
        FMA2(acc[0][0], mA.x, pw0, acc[0][0]); FMA2(acc[0][1], mA.x, pw1, acc[0][1]);
        FMA2(acc[0][2], mA.x, pw2, acc[0][2]); FMA2(acc[0][3], mA.x, pw3, acc[0][3]);
        FMA2(acc[1][0], mA.y, pw0, acc[1][0]); FMA2(acc[1][1], mA.y, pw1, acc[1][1]);
        FMA2(acc[1][2], mA.y, pw2, acc[1][2]); FMA2(acc[1][3], mA.y, pw3, acc[1][3]);
        FMA2(acc[2][0], mB.x, pw0, acc[2][0]); FMA2(acc[2][1], mB.x, pw1, acc[2][1]);
        FMA2(acc[2][2], mB.x, pw2, acc[2][2]); FMA2(acc[2][3], mB.x, pw3, acc[2][3]);
        FMA2(acc[3][0], mB.y, pw0, acc[3][0]); FMA2(acc[3][1], mB.y, pw1, acc[3][1]);
        FMA2(acc[3][2], mB.y, pw2, acc[3][2]); FMA2(acc[3][3], mB.y, pw3, acc[3][3]);
    }
    #pragma unroll
    for (int rp = 0; rp < 4; rp++) {
        float2 u0 = unpack2(acc[rp][0]), u1 = unpack2(acc[rp][1]);
        float2 u2 = unpack2(acc[rp][2]), u3 = unpack2(acc[rp][3]);
        float4 lo = make_float4(u0.x, u1.x, u2.x, u3.x);
        float4 hi = make_float4(u0.y, u1.y, u2.y, u3.y);
        *(float4*)&g_gpre[((size_t)(bl0 + 2*rp    ))*G4_ + n4] = lo;
        *(float4*)&g_gpre[((size_t)(bl0 + 2*rp + 1))*G4_ + n4] = hi;
    }
}

// ---------------- DSMEM helpers -----------------------------------------------------
__device__ __forceinline__ uint32_t smem_u32_(const void* p) {
    uint32_t a;
    asm("{ .reg .u64 t; cvta.to.shared.u64 t, %1; cvt.u32.u64 %0, t; }"
        : "=r"(a) : "l"(p));
    return a;
}
__device__ __forceinline__ void st_dsmem(uint32_t addr, float v) {
    asm volatile("st.shared::cluster.f32 [%0], %1;" :: "r"(addr), "f"(v) : "memory");
}
__device__ __forceinline__ void st_dsmem64(uint32_t addr, ull v) {
    asm volatile("st.shared::cluster.b64 [%0], %1;" :: "r"(addr), "l"(v) : "memory");
}
#define CLUSTER_SYNC_() do { \
    asm volatile("barrier.cluster.arrive.aligned;" ::: "memory"); \
    asm volatile("barrier.cluster.wait.aligned;"  ::: "memory"); } while (0)

// SMEM layout (floats)
#define HIST_STRIDE 260
#define FEAT_STRIDE 132
#define SOFF_WIHA  0
#define SOFF_HISTT (SOFF_WIHA + 128*256)                 // 32768
#define SOFF_FEATT (SOFF_HISTT + 32*HIST_STRIDE)         // 41088
#define SOFF_HDA   (SOFF_FEATT + 32*FEAT_STRIDE)         // 45312
#define SOFF_HDB   (SOFF_HDA + 2*256*8)                  // 49408
#define SOFF_XCB   (SOFF_HDB + 8*256)                    // 51456
#define SOFF_CC    (SOFF_XCB + 8*128)                    // 52480
#define SOFF_GT    (SOFF_CC + 128*8)                     // 53504
#define SOFF_NUM   (SOFF_GT + 8*256)                     // 55552
#define SMEM_FLOATS (SOFF_NUM + 16)
#define SMEM_BYTES (SMEM_FLOATS * 4)

__device__ __forceinline__ float sigm_(float x) { return 1.f / (1.f + __expf(-x)); }
__device__ __forceinline__ float tanh_(float x) { return 2.f / (1.f + __expf(-2.f*x)) - 1.f; }

// ---------------- K4: cluster-4 sequential recurrence (f32x2) -----------------------
__global__ void __launch_bounds__(256) __cluster_dims__(4, 1, 1)
k_main4(const float* __restrict__ values, const float* __restrict__ masks,
        const float* __restrict__ evalm,
        const float* __restrict__ hist_W, const float* __restrict__ feat_W,
        const float* __restrict__ hist_b, const float* __restrict__ feat_b,
        float* __restrict__ out)
{
    extern __shared__ float smf[];
    float* s_wihA  = smf + SOFF_WIHA;    // [128][256]
    float* s_histT = smf + SOFF_HISTT;   // [32][260]
    float* s_featT = smf + SOFF_FEATT;   // [32][132]
    float* s_hdA   = smf + SOFF_HDA;     // [2][256][8]
    float* s_hdB   = smf + SOFF_HDB;     // [8][256]
    float* s_xcB   = smf + SOFF_XCB;     // [8][128]
    float* s_cc    = smf + SOFF_CC;      // [128][8]
    float* s_gt    = smf + SOFF_GT;      // [8][256]
    float* s_num   = smf + SOFF_NUM;

    const int tid = threadIdx.x;
    uint32_t q;
    asm("mov.u32 %0, %%cluster_ctarank;" : "=r"(q));
    const int b0 = (blockIdx.x >> 2) * 8;

    // --- preload stationary slices ---
    #pragma unroll 4
    for (int i = tid; i < 128*256; i += 256) {
        int k = i >> 8, nn = i & 255;
        s_wihA[i] = g_WihA_t[k*G4_ + (int)q*256 + nn];
    }
    #pragma unroll 4
    for (int i = tid; i < 32*256; i += 256) {
        int dd = i >> 8, k = i & 255;
        s_histT[dd*HIST_STRIDE + k] = hist_W[((int)q*32 + dd)*H_ + k];
    }
    #pragma unroll 2
    for (int i = tid; i < 32*128; i += 256) {
        int dd = i >> 7, k = i & 127;
        int dg = (int)q*32 + dd;
        s_featT[dd*FEAT_STRIDE + k] = (k == dg) ? 0.f : feat_W[dg*D_ + k];
    }
    if (tid == 0) s_num[0] = 0.f;
    __syncthreads();

    // remote SMEM bases for the 4 ranks
    uint32_t sbase = smem_u32_(smf);
    uint32_t rb0, rb1, rb2, rb3;
    asm("mapa.shared::cluster.u32 %0, %1, %2;" : "=r"(rb0) : "r"(sbase), "r"(0u));
    asm("mapa.shared::cluster.u32 %0, %1, %2;" : "=r"(rb1) : "r"(sbase), "r"(1u));
    asm("mapa.shared::cluster.u32 %0, %1, %2;" : "=r"(rb2) : "r"(sbase), "r"(2u));
    asm("mapa.shared::cluster.u32 %0, %1, %2;" : "=r"(rb3) : "r"(sbase), "r"(3u));

    // thread mappings
    const int r1 = tid >> 5;                 // batch row 0..7 (one per warp)
    const int dd = tid & 31;                 // within-slice d
    const int dg = (int)q*32 + dd;           // global d
    const int jjA = dd*2;                    // two owned (local) h-indices
    const int jgA = (int)q*64 + jjA;         // global h index
    const float hb = hist_b[dg], fb = feat_b[dg];

    float hA = 0.f, hB = 0.f, cA = 0.f, cB = 0.f;

    for (int t = 0; t < L_; t++) {
        const int par = t & 1;

        // ---- P0: decay h, push hd (layouts A [k][row] and B [row][k]) ----
        {
            const float2 gg = *(const float2*)&g_gamma_h[((size_t)(b0+r1)*L_ + t)*H_ + jgA];
            float hdA = hA * gg.x;
            float hdB = hB * gg.y;
            uint32_t oA = (uint32_t)(SOFF_HDA + ((par*256 + jgA)*8 + r1)) * 4u;
            uint32_t oA2 = oA + 32u;
            ull hp = pack2(hdA, hdB);
            uint32_t oB = (uint32_t)(SOFF_HDB + (r1*256 + jgA)) * 4u;
            st_dsmem(rb0 + oA, hdA); st_dsmem(rb0 + oA2, hdB); st_dsmem64(rb0 + oB, hp);
            st_dsmem(rb1 + oA, hdA); st_dsmem(rb1 + oA2, hdB); st_dsmem64(rb1 + oB, hp);
            st_dsmem(rb2 + oA, hdA); st_dsmem(rb2 + oA2, hdB); st_dsmem64(rb2 + oB, hp);
            st_dsmem(rb3 + oA, hdA); st_dsmem(rb3 + oA2, hdB); st_dsmem64(rb3 + oB, hp);
        }
        CLUSTER_SYNC_();

        // ---- P1: x_h = hd . hist_row(dg) ; xc ; push xc ----
        const size_t ib = ((size_t)(b0+r1)*L_ + t)*D_ + dg;
        const float xv = values[ib];
        const float mv = masks[ib];
        float xh;
        {
            const float* hp = &s_hdB[r1*256];
            const float* wp = &s_histT[dd*HIST_STRIDE];
            ull a0 = 0, a1 = 0, a2 = 0, a3 = 0;
            #pragma unroll 8
            for (int k = 0; k < 256; k += 8) {
                ulonglong2 hv  = *(const ulonglong2*)(hp + k);
                ulonglong2 hv2 = *(const ulonglong2*)(hp + k + 4);
                ulonglong2 wv  = *(const ulonglong2*)(wp + k);
                ulonglong2 wv2 = *(const ulonglong2*)(wp + k + 4);
                FMA2(a0, hv.x,  wv.x,  a0);
                FMA2(a1, hv.y,  wv.y,  a1);
                FMA2(a2, hv2.x, wv2.x, a2);
                FMA2(a3, hv2.y, wv2.y, a3);
            }
            float2 p0 = unpack2(a0), p1 = unpack2(a1), p2 = unpack2(a2), p3 = unpack2(a3);
            xh = hb + ((p0.x + p0.y) + (p1.x + p1.y)) + ((p2.x + p2.y) + (p3.x + p3.y));
        }
        const float xc = mv*xv + (1.f - mv)*xh;
        {
            uint32_t o = (uint32_t)(SOFF_XCB + (r1*128 + dg)) * 4u;
            st_dsmem(rb0 + o, xc); st_dsmem(rb1 + o, xc);
            st_dsmem(rb2 + o, xc); st_dsmem(rb3 + o, xc);
        }
        CLUSTER_SYNC_();

        // ---- P2: z_h, c_h, c_c, imputation out, loss; push cc ----
        float cc;
        {
            const float* xp = &s_xcB[r1*128];
            const float* wp = &s_featT[dd*FEAT_STRIDE];
            ull a0 = 0, a1 = 0;
            #pragma unroll 8
            for (int k = 0; k < 128; k += 4) {
                ulonglong2 xv2 = *(const ulonglong2*)(xp + k);
                ulonglong2 wv2 = *(const ulonglong2*)(wp + k);
                FMA2(a0, xv2.x, wv2.x, a0);
                FMA2(a1, xv2.y, wv2.y, a1);
            }
            float2 p0 = unpack2(a0), p1 = unpack2(a1);
            float zh = fb + (p0.x + p0.y) + (p1.x + p1.y);
            float al = g_alpha[ib];
            float ch = al*zh + (1.f - al)*xh;
            cc = mv*xv + (1.f - mv)*ch;
            out[ib] = cc;
            float me = evalm[ib];
            float p = fabsf(cc - xv) * me;
            #pragma unroll
            for (int off = 16; off > 0; off >>= 1)
                p += __shfl_down_sync(0xffffffffu, p, off);
            if (dd == 0) atomicAdd(s_num, p);
            uint32_t o = (uint32_t)(SOFF_CC + (dg*8 + r1)) * 4u;
            st_dsmem(rb0 + o, cc); st_dsmem(rb1 + o, cc);
            st_dsmem(rb2 + o, cc); st_dsmem(rb3 + o, cc);
        }
        CLUSTER_SYNC_();

        // ---- P3: gates = gpre + hd@Whh-slice + cc@WihA-slice (own 256 n') ----
        if (tid == 0) {
            atomicAdd(&g_num[t], s_num[0]);
            s_num[0] = 0.f;
        }
        {
            ull acc[4];
            {
                const float* gp = &g_gpre[((size_t)b0*L_ + t)*G4_ + (int)q*256 + tid];
                float g0 = gp[0];
                float g1 = gp[(size_t)1*L_*G4_];
                float g2 = gp[(size_t)2*L_*G4_];
                float g3 = gp[(size_t)3*L_*G4_];
                float g4 = gp[(size_t)4*L_*G4_];
                float g5 = gp[(size_t)5*L_*G4_];
                float g6 = gp[(size_t)6*L_*G4_];
                float g7 = gp[(size_t)7*L_*G4_];
                acc[0] = pack2(g0, g1); acc[1] = pack2(g2, g3);
                acc[2] = pack2(g4, g5); acc[3] = pack2(g6, g7);
            }
            {
                const float* wp  = &g_Whh_t[(int)q*256 + tid];
                const float* hdp = &s_hdA[par*256*8];
                #pragma unroll 8
                for (int k = 0; k < 256; k++) {
                    float w = wp[k*G4_];
                    ull ww = bcast2(w);
                    ulonglong2 u = *(const ulonglong2*)(hdp + k*8);
                    ulonglong2 v = *(const ulonglong2*)(hdp + k*8 + 4);
                    FMA2(acc[0], u.x, ww, acc[0]);
                    FMA2(acc[1], u.y, ww, acc[1]);
                    FMA2(acc[2], v.x, ww, acc[2]);
                    FMA2(acc[3], v.y, ww, acc[3]);
                }
            }
            {
                #pragma unroll 8
                for (int k = 0; k < 128; k++) {
                    float w = s_wihA[k*256 + tid];
                    ull ww = bcast2(w);
                    ulonglong2 u = *(const ulonglong2*)(s_cc + k*8);
                    ulonglong2 v = *(const ulonglong2*)(s_cc + k*8 + 4);
                    FMA2(acc[0], u.x, ww, acc[0]);
                    FMA2(acc[1], u.y, ww, acc[1]);
                    FMA2(acc[2], v.x, ww, acc[2]);
                    FMA2(acc[3], v.y, ww, acc[3]);
                }
            }
            #pragma unroll
            for (int rp = 0; rp < 4; rp++) {
                float2 u = unpack2(acc[rp]);
                s_gt[(2*rp    )*256 + tid] = u.x;
                s_gt[(2*rp + 1)*256 + tid] = u.y;
            }
        }
        __syncthreads();

        // ---- P4: LSTM elementwise for (row r1, local j = jjA, jjA+1) ----
        {
            const float* gr = &s_gt[r1*256];
            float2 ii = *(const float2*)(gr + jjA);
            float2 ff = *(const float2*)(gr + 64 + jjA);
            float2 gg = *(const float2*)(gr + 128 + jjA);
            float2 oo = *(const float2*)(gr + 192 + jjA);
            float i0 = sigm_(ii.x), f0 = sigm_(ff.x), o0 = sigm_(oo.x), g0 = tanh_(gg.x);
            float i1 = sigm_(ii.y), f1 = sigm_(ff.y), o1 = sigm_(oo.y), g1 = tanh_(gg.y);
            cA = f0*cA + i0*g0;  hA = o0 * tanh_(cA);
            cB = f1*cB + i1*g1;  hB = o1 * tanh_(cB);
        }
        // no extra barrier: s_hdA double-buffered (par); s_hdB/s_xcB/s_cc/s_gt
        // rewrites are separated by >=1 cluster sync from their last reads.
    }
}

// ---------------- K5: finalize loss -------------------------------------------------
__global__ void k_fin(float* __restrict__ out, int out_size)
{
    int t = threadIdx.x;
    float v = g_num[t] / (g_den[t] + 1e-5f);
    #pragma unroll
    for (int off = 16; off > 0; off >>= 1)
        v += __shfl_down_sync(0xffffffffu, v, off);
    __shared__ float red[8];
    if ((t & 31) == 0) red[t >> 5] = v;
    __syncthreads();
    if (t == 0) {
        float s = 0.f;
        #pragma unroll
        for (int i = 0; i < 8; i++) s += red[i];
        if (out_size > B_*L_*D_) out[B_*L_*D_] = s;
    }
}

// ---------------- launch -------------------------------------------------------------
extern "C" void kernel_launch(void* const* d_in, const int* in_sizes, int n_in,
                              void* d_out, int out_size)
{
    const float* values = (const float*)d_in[0];
    const float* masks  = (const float*)d_in[1];
    const float* deltas = (const float*)d_in[2];
    const float* evalm  = (const float*)d_in[3];
    const float* td_h_W = (const float*)d_in[4];
    const float* td_h_b = (const float*)d_in[5];
    const float* td_x_w = (const float*)d_in[6];
    const float* td_x_b = (const float*)d_in[7];
    const float* hist_W = (const float*)d_in[8];
    const float* hist_b = (const float*)d_in[9];
    const float* feat_W = (const float*)d_in[10];
    const float* feat_b = (const float*)d_in[11];
    const float* wc_W   = (const float*)d_in[12];
    const float* wc_b   = (const float*)d_in[13];
    const float* W_ih   = (const float*)d_in[14];
    const float* W_hh   = (const float*)d_in[15];
    const float* b_ih   = (const float*)d_in[16];
    const float* b_hh   = (const float*)d_in[17];
    float* out = (float*)d_out;

    cudaFuncSetAttribute(k_main4, cudaFuncAttributeMaxDynamicSharedMemorySize, SMEM_BYTES);

    k_prep   <<<256, 256>>>(W_ih, W_hh, td_h_W, wc_W, b_ih, b_hh);
    k_den    <<<L_, 128>>>(evalm);
    k_gamma_h<<<BL_/16, 256>>>(deltas, td_h_b);
    k_alpha  <<<BL_/16, 128>>>(deltas, masks, td_x_w, td_x_b, wc_b);
    k_gpre   <<<BL_/8, 256>>>(masks);
    k_main4  <<<128, 256, SMEM_BYTES>>>(values, masks, evalm, hist_W, feat_W,
                                        hist_b, feat_b, out);
    k_fin    <<<1, 256>>>(out, out_size);
}

// round 6
// speedup vs baseline: 2.5612x; 1.0808x over previous
#include <cuda_runtime.h>
#include <math.h>
#include <stdint.h>

#define B_  256
#define L_  256
#define D_  128
#define H_  256
#define G4_ 1024
#define BL_ (B_*L_)

typedef unsigned long long ull;

// ---------------- f32x2 helpers ---------------------------------------------------
#define FMA2(d,a,b,c) asm("fma.rn.f32x2 %0, %1, %2, %3;" : "=l"(d) : "l"(a), "l"(b), "l"(c))
__device__ __forceinline__ ull bcast2(float v){ ull d; asm("mov.b64 %0, {%1, %1};" : "=l"(d) : "f"(v)); return d; }
__device__ __forceinline__ ull pack2(float lo, float hi){ ull d; asm("mov.b64 %0, {%1, %2};" : "=l"(d) : "f"(lo), "f"(hi)); return d; }
__device__ __forceinline__ float2 unpack2(ull d){ float lo,hi; asm("mov.b64 {%0, %1}, %2;" : "=f"(lo), "=f"(hi) : "l"(d)); return make_float2(lo,hi); }

// ---------------- device scratch (static; no allocations anywhere) ----------------
__device__ float g_gamma_h[BL_*H_];            // 64 MB
__device__ float g_alpha  [BL_*D_];            // 32 MB
// cluster-grouped: [bg(32)][t(256)][q(4)][r(8)][nn(256)]
__device__ float g_gpre   [(size_t)BL_*G4_];   // 256 MB
// per-CTA-contiguous: [q(4)][k(256)][nn(256)]
__device__ float g_Whh_q  [H_*G4_];
__device__ float g_WihA_t [D_*G4_];            // [k][n'] permuted
__device__ float g_WihB_t [D_*G4_];            // [k][n'] permuted
__device__ float g_tdh_t  [D_*H_];             // [d][j]
__device__ float g_wc_t   [(2*D_)*D_];         // [k][dn]
__device__ float g_bias   [G4_];               // permuted b_ih+b_hh
__device__ float g_num    [L_];
__device__ float g_den    [L_];

// gate-column permutation: n' = q*256 + g*64 + jj  <->  n = g*256 + q*64 + jj
__device__ __forceinline__ int permN(int np) {
    return ((np >> 6) & 3) * 256 + (np >> 8) * 64 + (np & 63);
}

// ---------------- K0: weight transposes (permuted) + zero g_num -------------------
__global__ void k_prep(const float* __restrict__ W_ih,   const float* __restrict__ W_hh,
                       const float* __restrict__ td_h_W, const float* __restrict__ wc_W,
                       const float* __restrict__ b_ih,   const float* __restrict__ b_hh)
{
    int idx = blockIdx.x * blockDim.x + threadIdx.x;
    int stride = gridDim.x * blockDim.x;
    for (int i = idx; i < H_*G4_; i += stride) {
        // [q][k][nn] = W_hh[permN(q*256+nn)][k]
        int q = i >> 16, k = (i >> 8) & 255, nn = i & 255;
        g_Whh_q[i] = W_hh[permN(q*256 + nn)*H_ + k];
    }
    for (int i = idx; i < D_*G4_; i += stride) {
        int k = i >> 10, np = i & 1023;
        int n = permN(np);
        g_WihA_t[i] = W_ih[n*(2*D_) + k];
        g_WihB_t[i] = W_ih[n*(2*D_) + D_ + k];
    }
    for (int i = idx; i < D_*H_; i += stride) {
        int d = i / H_, j = i % H_;
        g_tdh_t[i] = td_h_W[j*D_ + d];
    }
    for (int i = idx; i < (2*D_)*D_; i += stride) {
        int k = i / D_, dn = i % D_;
        g_wc_t[i] = wc_W[dn*(2*D_) + k];
    }
    for (int i = idx; i < G4_; i += stride) {
        int n = permN(i);
        g_bias[i] = b_ih[n] + b_hh[n];
    }
    for (int i = idx; i < L_;  i += stride) g_num[i] = 0.f;
}

// ---------------- K0b: per-timestep loss denominator ------------------------------
__global__ void k_den(const float* __restrict__ evalm)
{
    int t = blockIdx.x;
    int tid = threadIdx.x;
    float s = 0.f;
    for (int b = 0; b < B_; b++)
        s += evalm[((size_t)b*L_ + t)*D_ + tid];
    #pragma unroll
    for (int off = 16; off > 0; off >>= 1)
        s += __shfl_down_sync(0xffffffffu, s, off);
    __shared__ float red[4];
    if ((tid & 31) == 0) red[tid >> 5] = s;
    __syncthreads();
    if (tid == 0) g_den[t] = red[0] + red[1] + red[2] + red[3];
}

// ---------------- K1: gamma_h precompute -------------------------------------------
__global__ void __launch_bounds__(256) k_gamma_h(const float* __restrict__ deltas,
                                                 const float* __restrict__ td_h_b)
{
    __shared__ float sd[16][D_];
    int bl0 = blockIdx.x * 16;
    int tid = threadIdx.x;
    #pragma unroll
    for (int i = 0; i < 8; i++) {
        int idx = tid + i*256;
        int r = idx >> 7, d = idx & 127;
        sd[r][d] = deltas[(size_t)(bl0 + r)*D_ + d];
    }
    __syncthreads();
    int j = tid;
    float acc[16];
    float b = td_h_b[j];
    #pragma unroll
    for (int r = 0; r < 16; r++) acc[r] = b;
    #pragma unroll 4
    for (int d = 0; d < D_; d++) {
        float w = g_tdh_t[d*H_ + j];
        #pragma unroll
        for (int r = 0; r < 16; r++) acc[r] += sd[r][d] * w;
    }
    #pragma unroll
    for (int r = 0; r < 16; r++)
        g_gamma_h[(size_t)(bl0 + r)*H_ + j] = __expf(-fmaxf(acc[r], 0.f));
}

// ---------------- K2: alpha precompute ---------------------------------------------
__global__ void __launch_bounds__(128) k_alpha(const float* __restrict__ deltas,
                                               const float* __restrict__ masks,
                                               const float* __restrict__ td_x_w,
                                               const float* __restrict__ td_x_b,
                                               const float* __restrict__ wc_b)
{
    __shared__ float sin_[16][2*D_];
    int bl0 = blockIdx.x * 16;
    int tid = threadIdx.x;
    #pragma unroll
    for (int i = 0; i < 32; i++) {
        int idx = tid + i*128;
        int r = idx >> 8, k = idx & 255;
        float v;
        if (k < D_) {
            float dd = deltas[(size_t)(bl0 + r)*D_ + k];
            v = __expf(-fmaxf(dd*td_x_w[k] + td_x_b[k], 0.f));
        } else {
            v = masks[(size_t)(bl0 + r)*D_ + (k - D_)];
        }
        sin_[r][k] = v;
    }
    __syncthreads();
    int dn = tid;
    float acc[16];
    float b = wc_b[dn];
    #pragma unroll
    for (int r = 0; r < 16; r++) acc[r] = b;
    #pragma unroll 4
    for (int k = 0; k < 2*D_; k++) {
        float w = g_wc_t[k*D_ + dn];
        #pragma unroll
        for (int r = 0; r < 16; r++) acc[r] += sin_[r][k] * w;
    }
    #pragma unroll
    for (int r = 0; r < 16; r++)
        g_alpha[(size_t)(bl0 + r)*D_ + dn] = acc[r];
}

// ---------------- K3: gates m-half precompute (cluster-grouped layout) --------------
__global__ void __launch_bounds__(256) k_gpre(const float* __restrict__ masks)
{
    __shared__ float sm[D_*8];      // [d][row]
    int bl0 = blockIdx.x * 8;       // 8 consecutive bl = same b, t0..t0+7
    int tid = threadIdx.x;
    #pragma unroll
    for (int i = 0; i < 4; i++) {
        int idx = tid + i*256;
        int r = idx >> 7, d = idx & 127;
        sm[d*8 + r] = masks[(size_t)(bl0 + r)*D_ + d];
    }
    __syncthreads();
    int n4 = tid * 4;
    float4 bias4 = *(const float4*)&g_bias[n4];
    ull acc[4][4];                  // [rowpair][col]
    #pragma unroll
    for (int rp = 0; rp < 4; rp++) {
        acc[rp][0] = bcast2(bias4.x); acc[rp][1] = bcast2(bias4.y);
        acc[rp][2] = bcast2(bias4.z); acc[rp][3] = bcast2(bias4.w);
    }
    #pragma unroll 4
    for (int k = 0; k < D_; k++) {
        float4 w = *(const float4*)&g_WihB_t[k*G4_ + n4];
        ull pw0 = bcast2(w.x), pw1 = bcast2(w.y), pw2 = bcast2(w.z), pw3 = bcast2(w.w);
        ulonglong2 mA = *(const ulonglong2*)&sm[k*8];
        ulonglong2 mB = *(const ulonglong2*)&sm[k*8 + 4];
        FMA2(acc[0][0], mA.x, pw0, acc[0][0]); FMA2(acc[0][1], mA.x, pw1, acc[0][1]);
        FMA2(acc[0][2], mA.x, pw2, acc[0][2]); FMA2(acc[0][3], mA.x, pw3, acc[0][3]);
        FMA2(acc[1][0], mA.y, pw0, acc[1][0]); FMA2(acc[1][1], mA.y, pw1, acc[1][1]);
        FMA2(acc[1][2], mA.y, pw2, acc[1][2]); FMA2(acc[1][3], mA.y, pw3, acc[1][3]);
        FMA2(acc[2][0], mB.x, pw0, acc[2][0]); FMA2(acc[2][1], mB.x, pw1, acc[2][1]);
        FMA2(acc[2][2], mB.x, pw2, acc[2][2]); FMA2(acc[2][3], mB.x, pw3, acc[2][3]);
        FMA2(acc[3][0], mB.y, pw0, acc[3][0]); FMA2(acc[3][1], mB.y, pw1, acc[3][1]);
        FMA2(acc[3][2], mB.y, pw2, acc[3][2]); FMA2(acc[3][3], mB.y, pw3, acc[3][3]);
    }
    // write cluster-grouped: [bg][t][q][r][nn]
    int b = bl0 >> 8, t0c = bl0 & 255;
    int bg = b >> 3, r = b & 7;
    int q = tid >> 6, nn = n4 & 255;
    #pragma unroll
    for (int rp = 0; rp < 4; rp++) {
        float2 u0 = unpack2(acc[rp][0]), u1 = unpack2(acc[rp][1]);
        float2 u2 = unpack2(acc[rp][2]), u3 = unpack2(acc[rp][3]);
        float4 lo = make_float4(u0.x, u1.x, u2.x, u3.x);
        float4 hi = make_float4(u0.y, u1.y, u2.y, u3.y);
        size_t aLo = ((((size_t)bg*256 + t0c + 2*rp    )*4 + q)*8 + r)*256 + nn;
        size_t aHi = ((((size_t)bg*256 + t0c + 2*rp + 1)*4 + q)*8 + r)*256 + nn;
        *(float4*)&g_gpre[aLo] = lo;
        *(float4*)&g_gpre[aHi] = hi;
    }
}

// ---------------- DSMEM helpers -----------------------------------------------------
__device__ __forceinline__ uint32_t smem_u32_(const void* p) {
    uint32_t a;
    asm("{ .reg .u64 t; cvta.to.shared.u64 t, %1; cvt.u32.u64 %0, t; }"
        : "=r"(a) : "l"(p));
    return a;
}
__device__ __forceinline__ void st_dsmem(uint32_t addr, float v) {
    asm volatile("st.shared::cluster.f32 [%0], %1;" :: "r"(addr), "f"(v) : "memory");
}
__device__ __forceinline__ void st_dsmem64(uint32_t addr, ull v) {
    asm volatile("st.shared::cluster.b64 [%0], %1;" :: "r"(addr), "l"(v) : "memory");
}
#define CLUSTER_SYNC_() do { \
    asm volatile("barrier.cluster.arrive.aligned;" ::: "memory"); \
    asm volatile("barrier.cluster.wait.aligned;"  ::: "memory"); } while (0)

// SMEM layout (floats)
#define HIST_STRIDE 260
#define FEAT_STRIDE 132
#define SOFF_WIHA  0
#define SOFF_HISTT (SOFF_WIHA + 128*256)                 // 32768
#define SOFF_FEATT (SOFF_HISTT + 32*HIST_STRIDE)         // 41088
#define SOFF_HDA   (SOFF_FEATT + 32*FEAT_STRIDE)         // 45312
#define SOFF_HDB   (SOFF_HDA + 2*256*8)                  // 49408
#define SOFF_XCB   (SOFF_HDB + 8*256)                    // 51456
#define SOFF_CC    (SOFF_XCB + 8*128)                    // 52480
#define SOFF_GT    (SOFF_CC + 128*8)                     // 53504
#define SOFF_NUM   (SOFF_GT + 8*256)                     // 55552
#define SMEM_FLOATS (SOFF_NUM + 16)
#define SMEM_BYTES (SMEM_FLOATS * 4)

__device__ __forceinline__ float sigm_(float x) { return 1.f / (1.f + __expf(-x)); }
__device__ __forceinline__ float tanh_(float x) { return 2.f / (1.f + __expf(-2.f*x)) - 1.f; }

// ---------------- K4: cluster-4 sequential recurrence (latency-hidden) --------------
__global__ void __launch_bounds__(256) __cluster_dims__(4, 1, 1)
k_main4(const float* __restrict__ values, const float* __restrict__ masks,
        const float* __restrict__ evalm,
        const float* __restrict__ hist_W, const float* __restrict__ feat_W,
        const float* __restrict__ hist_b, const float* __restrict__ feat_b,
        float* __restrict__ out)
{
    extern __shared__ float smf[];
    float* s_wihA  = smf + SOFF_WIHA;    // [128][256]
    float* s_histT = smf + SOFF_HISTT;   // [32][260]
    float* s_featT = smf + SOFF_FEATT;   // [32][132]
    float* s_hdA   = smf + SOFF_HDA;     // [2][256][8]
    float* s_hdB   = smf + SOFF_HDB;     // [8][256]
    float* s_xcB   = smf + SOFF_XCB;     // [8][128]
    float* s_cc    = smf + SOFF_CC;      // [128][8]
    float* s_gt    = smf + SOFF_GT;      // [8][256]
    float* s_num   = smf + SOFF_NUM;

    const int tid = threadIdx.x;
    uint32_t q;
    asm("mov.u32 %0, %%cluster_ctarank;" : "=r"(q));
    const int bg = blockIdx.x >> 2;
    const int b0 = bg * 8;

    // --- preload stationary slices ---
    #pragma unroll 4
    for (int i = tid; i < 128*256; i += 256) {
        int k = i >> 8, nn = i & 255;
        s_wihA[i] = g_WihA_t[k*G4_ + (int)q*256 + nn];
    }
    #pragma unroll 4
    for (int i = tid; i < 32*256; i += 256) {
        int dd = i >> 8, k = i & 255;
        s_histT[dd*HIST_STRIDE + k] = hist_W[((int)q*32 + dd)*H_ + k];
    }
    #pragma unroll 2
    for (int i = tid; i < 32*128; i += 256) {
        int dd = i >> 7, k = i & 127;
        int dg = (int)q*32 + dd;
        s_featT[dd*FEAT_STRIDE + k] = (k == dg) ? 0.f : feat_W[dg*D_ + k];
    }
    if (tid == 0) s_num[0] = 0.f;
    __syncthreads();

    // remote SMEM bases for the 4 ranks
    uint32_t sbase = smem_u32_(smf);
    uint32_t rb0, rb1, rb2, rb3;
    asm("mapa.shared::cluster.u32 %0, %1, %2;" : "=r"(rb0) : "r"(sbase), "r"(0u));
    asm("mapa.shared::cluster.u32 %0, %1, %2;" : "=r"(rb1) : "r"(sbase), "r"(1u));
    asm("mapa.shared::cluster.u32 %0, %1, %2;" : "=r"(rb2) : "r"(sbase), "r"(2u));
    asm("mapa.shared::cluster.u32 %0, %1, %2;" : "=r"(rb3) : "r"(sbase), "r"(3u));

    // thread mappings
    const int r1 = tid >> 5;                 // batch row 0..7 (one per warp)
    const int dd = tid & 31;                 // within-slice d
    const int dg = (int)q*32 + dd;           // global d
    const int jjA = dd*2;                    // two owned (local) h-indices
    const int jgA = (int)q*64 + jjA;         // global h index
    const float hb = hist_b[dg], fb = feat_b[dg];

    const size_t ib0   = ((size_t)(b0+r1)*L_)*D_ + dg;    // + t*D_
    const size_t gam0  = ((size_t)(b0+r1)*L_)*H_ + jgA;   // + t*H_
    const float* wp    = g_Whh_q + ((size_t)q << 16) + tid;
    const float* gp0   = g_gpre + (((size_t)bg*256*4 + q)*8)*256 + tid;  // + t*4*8*256

    float hA = 0.f, hB = 0.f, cA = 0.f, cB = 0.f;

    // rotated prefetch registers (step 0)
    float2 gg   = *(const float2*)&g_gamma_h[gam0];
    float  xv_n = values[ib0];
    float  mv_n = masks[ib0];
    float  al_n = g_alpha[ib0];
    float  ev_n = evalm[ib0];

    for (int t = 0; t < L_; t++) {
        const int par = t & 1;
        const int tn = (t + 1) & 255;         // wrapped (last iter value unused)

        // ---- gpre prefetch for THIS step (consumed in P3, ~3 phases away) ----
        float g8[8];
        {
            const float* gp = gp0 + (size_t)t*(4*8*256);
            #pragma unroll
            for (int r = 0; r < 8; r++) g8[r] = gp[r*256];
        }

        // ---- P0: decay h, push hd (layouts A [k][row] and B [row][k]) ----
        {
            float hdA = hA * gg.x;
            float hdB = hB * gg.y;
            uint32_t oA = (uint32_t)(SOFF_HDA + ((par*256 + jgA)*8 + r1)) * 4u;
            uint32_t oA2 = oA + 32u;
            ull hp = pack2(hdA, hdB);
            uint32_t oB = (uint32_t)(SOFF_HDB + (r1*256 + jgA)) * 4u;
            st_dsmem(rb0 + oA, hdA); st_dsmem(rb0 + oA2, hdB); st_dsmem64(rb0 + oB, hp);
            st_dsmem(rb1 + oA, hdA); st_dsmem(rb1 + oA2, hdB); st_dsmem64(rb1 + oB, hp);
            st_dsmem(rb2 + oA, hdA); st_dsmem(rb2 + oA2, hdB); st_dsmem64(rb2 + oB, hp);
            st_dsmem(rb3 + oA, hdA); st_dsmem(rb3 + oA2, hdB); st_dsmem64(rb3 + oB, hp);
            // prefetch next-step gamma (full-step slack)
            gg = *(const float2*)&g_gamma_h[gam0 + (size_t)tn*H_];
        }
        CLUSTER_SYNC_();

        // ---- P1: x_h = hd . hist_row(dg) ; xc ; push xc ----
        const size_t ib = ib0 + (size_t)t*D_;
        const float xv = xv_n;
        const float mv = mv_n;
        {   // prefetch next-step x/m
            const size_t ibn = ib0 + (size_t)tn*D_;
            xv_n = values[ibn];
            mv_n = masks[ibn];
        }
        float xh;
        {
            const float* hp = &s_hdB[r1*256];
            const float* wpt = &s_histT[dd*HIST_STRIDE];
            ull a0 = 0, a1 = 0, a2 = 0, a3 = 0;
            #pragma unroll 8
            for (int k = 0; k < 256; k += 8) {
                ulonglong2 hv  = *(const ulonglong2*)(hp + k);
                ulonglong2 hv2 = *(const ulonglong2*)(hp + k + 4);
                ulonglong2 wv  = *(const ulonglong2*)(wpt + k);
                ulonglong2 wv2 = *(const ulonglong2*)(wpt + k + 4);
                FMA2(a0, hv.x,  wv.x,  a0);
                FMA2(a1, hv.y,  wv.y,  a1);
                FMA2(a2, hv2.x, wv2.x, a2);
                FMA2(a3, hv2.y, wv2.y, a3);
            }
            float2 p0 = unpack2(a0), p1 = unpack2(a1), p2 = unpack2(a2), p3 = unpack2(a3);
            xh = hb + ((p0.x + p0.y) + (p1.x + p1.y)) + ((p2.x + p2.y) + (p3.x + p3.y));
        }
        const float xc = mv*xv + (1.f - mv)*xh;
        {
            uint32_t o = (uint32_t)(SOFF_XCB + (r1*128 + dg)) * 4u;
            st_dsmem(rb0 + o, xc); st_dsmem(rb1 + o, xc);
            st_dsmem(rb2 + o, xc); st_dsmem(rb3 + o, xc);
        }
        CLUSTER_SYNC_();

        // ---- P2: z_h, c_h, c_c, imputation out, loss; push cc ----
        float cc;
        {
            const float al = al_n;
            const float me = ev_n;
            {   // prefetch next-step alpha/evalm
                const size_t ibn = ib0 + (size_t)tn*D_;
                al_n = g_alpha[ibn];
                ev_n = evalm[ibn];
            }
            const float* xp = &s_xcB[r1*128];
            const float* wpt = &s_featT[dd*FEAT_STRIDE];
            ull a0 = 0, a1 = 0;
            #pragma unroll 8
            for (int k = 0; k < 128; k += 4) {
                ulonglong2 xv2 = *(const ulonglong2*)(xp + k);
                ulonglong2 wv2 = *(const ulonglong2*)(wpt + k);
                FMA2(a0, xv2.x, wv2.x, a0);
                FMA2(a1, xv2.y, wv2.y, a1);
            }
            float2 p0 = unpack2(a0), p1 = unpack2(a1);
            float zh = fb + (p0.x + p0.y) + (p1.x + p1.y);
            float ch = al*zh + (1.f - al)*xh;
            cc = mv*xv + (1.f - mv)*ch;
            out[ib] = cc;
            float p = fabsf(cc - xv) * me;
            #pragma unroll
            for (int off = 16; off > 0; off >>= 1)
                p += __shfl_down_sync(0xffffffffu, p, off);
            if (dd == 0) atomicAdd(s_num, p);
            uint32_t o = (uint32_t)(SOFF_CC + (dg*8 + r1)) * 4u;
            st_dsmem(rb0 + o, cc); st_dsmem(rb1 + o, cc);
            st_dsmem(rb2 + o, cc); st_dsmem(rb3 + o, cc);
        }
        CLUSTER_SYNC_();

        // ---- P3: gates = gpre + hd@Whh-slice + cc@WihA-slice (own 256 n') ----
        if (tid == 0) {
            atomicAdd(&g_num[t], s_num[0]);
            s_num[0] = 0.f;
        }
        {
            ull acc[4];
            acc[0] = pack2(g8[0], g8[1]); acc[1] = pack2(g8[2], g8[3]);
            acc[2] = pack2(g8[4], g8[5]); acc[3] = pack2(g8[6], g8[7]);
            {
                const float* hdp = &s_hdA[par*256*8];
                #pragma unroll 16
                for (int k = 0; k < 256; k++) {
                    ull ww = bcast2(wp[k*256]);           // contiguous-k L2 stream
                    ulonglong2 u = *(const ulonglong2*)(hdp + k*8);
                    ulonglong2 v = *(const ulonglong2*)(hdp + k*8 + 4);
                    FMA2(acc[0], u.x, ww, acc[0]);
                    FMA2(acc[1], u.y, ww, acc[1]);
                    FMA2(acc[2], v.x, ww, acc[2]);
                    FMA2(acc[3], v.y, ww, acc[3]);
                }
            }
            {
                #pragma unroll 8
                for (int k = 0; k < 128; k++) {
                    ull ww = bcast2(s_wihA[k*256 + tid]);
                    ulonglong2 u = *(const ulonglong2*)(s_cc + k*8);
                    ulonglong2 v = *(const ulonglong2*)(s_cc + k*8 + 4);
                    FMA2(acc[0], u.x, ww, acc[0]);
                    FMA2(acc[1], u.y, ww, acc[1]);
                    FMA2(acc[2], v.x, ww, acc[2]);
                    FMA2(acc[3], v.y, ww, acc[3]);
                }
            }
            #pragma unroll
            for (int rp = 0; rp < 4; rp++) {
                float2 u = unpack2(acc[rp]);
                s_gt[(2*rp    )*256 + tid] = u.x;
                s_gt[(2*rp + 1)*256 + tid] = u.y;
            }
        }
        __syncthreads();

        // ---- P4: LSTM elementwise for (row r1, local j = jjA, jjA+1) ----
        {
            const float* gr = &s_gt[r1*256];
            float2 ii = *(const float2*)(gr + jjA);
            float2 ff = *(const float2*)(gr + 64 + jjA);
            float2 gv = *(const float2*)(gr + 128 + jjA);
            float2 oo = *(const float2*)(gr + 192 + jjA);
            float i0 = sigm_(ii.x), f0 = sigm_(ff.x), o0 = sigm_(oo.x), g0 = tanh_(gv.x);
            float i1 = sigm_(ii.y), f1 = sigm_(ff.y), o1 = sigm_(oo.y), g1 = tanh_(gv.y);
            cA = f0*cA + i0*g0;  hA = o0 * tanh_(cA);
            cB = f1*cB + i1*g1;  hB = o1 * tanh_(cB);
        }
        // s_hdA double-buffered (par); s_hdB/s_xcB/s_cc/s_gt rewrites are
        // separated by >=1 cluster sync from their last reads.
    }
}

// ---------------- K5: finalize loss -------------------------------------------------
__global__ void k_fin(float* __restrict__ out, int out_size)
{
    int t = threadIdx.x;
    float v = g_num[t] / (g_den[t] + 1e-5f);
    #pragma unroll
    for (int off = 16; off > 0; off >>= 1)
        v += __shfl_down_sync(0xffffffffu, v, off);
    __shared__ float red[8];
    if ((t & 31) == 0) red[t >> 5] = v;
    __syncthreads();
    if (t == 0) {
        float s = 0.f;
        #pragma unroll
        for (int i = 0; i < 8; i++) s += red[i];
        if (out_size > B_*L_*D_) out[B_*L_*D_] = s;
    }
}

// ---------------- launch -------------------------------------------------------------
extern "C" void kernel_launch(void* const* d_in, const int* in_sizes, int n_in,
                              void* d_out, int out_size)
{
    const float* values = (const float*)d_in[0];
    const float* masks  = (const float*)d_in[1];
    const float* deltas = (const float*)d_in[2];
    const float* evalm  = (const float*)d_in[3];
    const float* td_h_W = (const float*)d_in[4];
    const float* td_h_b = (const float*)d_in[5];
    const float* td_x_w = (const float*)d_in[6];
    const float* td_x_b = (const float*)d_in[7];
    const float* hist_W = (const float*)d_in[8];
    const float* hist_b = (const float*)d_in[9];
    const float* feat_W = (const float*)d_in[10];
    const float* feat_b = (const float*)d_in[11];
    const float* wc_W   = (const float*)d_in[12];
    const float* wc_b   = (const float*)d_in[13];
    const float* W_ih   = (const float*)d_in[14];
    const float* W_hh   = (const float*)d_in[15];
    const float* b_ih   = (const float*)d_in[16];
    const float* b_hh   = (const float*)d_in[17];
    float* out = (float*)d_out;

    cudaFuncSetAttribute(k_main4, cudaFuncAttributeMaxDynamicSharedMemorySize, SMEM_BYTES);

    k_prep   <<<256, 256>>>(W_ih, W_hh, td_h_W, wc_W, b_ih, b_hh);
    k_den    <<<L_, 128>>>(evalm);
    k_gamma_h<<<BL_/16, 256>>>(deltas, td_h_b);
    k_alpha  <<<BL_/16, 128>>>(deltas, masks, td_x_w, td_x_b, wc_b);
    k_gpre   <<<BL_/8, 256>>>(masks);
    k_main4  <<<128, 256, SMEM_BYTES>>>(values, masks, evalm, hist_W, feat_W,
                                        hist_b, feat_b, out);
    k_fin    <<<1, 256>>>(out, out_size);
}